// round 2
// baseline (speedup 1.0000x reference)
#include <cuda_runtime.h>

#define NN 50000
#define NE 800000
#define DD 256
#define LAT 128

// ---------------- scratch (static __device__ globals; no allocs) ----------
static __device__ int   g_is64;
static __device__ int   g_deg[NN];
static __device__ float g_dinv[NN];
static __device__ int   g_src[NE];
static __device__ int   g_dst[NE];
static __device__ float g_nrm[NE];
static __device__ __align__(16) float g_s1[(size_t)NN * DD];
static __device__ __align__(16) float g_z [(size_t)NN * DD];
static __device__ __align__(16) float g_s2[(size_t)NN * DD];

// ---------------- small prep kernels --------------------------------------
__global__ void zero_deg_kernel() {
    int i = blockIdx.x * blockDim.x + threadIdx.x;
    if (i < NN) g_deg[i] = 0;
}

// Detect whether edge_index is int64 or int32 (JAX w/o x64 downgrades to i32).
__global__ void detect_kernel(const void* ei) {
    const long long* p = (const long long*)ei;
    int ok = 1;
    for (int i = 0; i < 256; i++) {
        long long v = p[i];
        if (v < 0 || v >= NN) { ok = 0; break; }
    }
    g_is64 = ok;
}

__device__ __forceinline__ int load_idx(const void* ei, int pos) {
    if (g_is64) return (int)((const long long*)ei)[pos];
    return ((const int*)ei)[pos];
}

__global__ void count_deg_kernel(const void* __restrict__ ei) {
    int e = blockIdx.x * blockDim.x + threadIdx.x;
    if (e < NE) {
        int d = load_idx(ei, NE + e);
        atomicAdd(&g_deg[d], 1);
    }
}

__global__ void dinv_kernel() {
    int i = blockIdx.x * blockDim.x + threadIdx.x;
    if (i < NN) g_dinv[i] = rsqrtf((float)g_deg[i] + 1.0f);
}

__global__ void edge_meta_kernel(const void* __restrict__ ei) {
    int e = blockIdx.x * blockDim.x + threadIdx.x;
    if (e < NE) {
        int s = load_idx(ei, e);
        int d = load_idx(ei, NE + e);
        g_src[e] = s;
        g_dst[e] = d;
        g_nrm[e] = g_dinv[s] * g_dinv[d];
    }
}

// s1[i,:] = x[i,:] * dinv[i]^2   (self-loop contribution, pre-GEMM)
__global__ void init_s1_kernel(const float4* __restrict__ x4) {
    int idx = blockIdx.x * blockDim.x + threadIdx.x;   // one float4 each
    if (idx < NN * (DD / 4)) {
        int row = idx >> 6;                             // DD/4 = 64
        float d = g_dinv[row];
        float d2 = d * d;
        float4 v = x4[idx];
        v.x *= d2; v.y *= d2; v.z *= d2; v.w *= d2;
        ((float4*)g_s1)[idx] = v;
    }
}

// ---------------- edge scatter: acc[dst,:] += feat[src,:] * norm ----------
// 256 threads, 64 edges/block; each thread handles one float4 per edge-group.
__global__ void __launch_bounds__(256) scatter_kernel(
        const float4* __restrict__ feat, float* __restrict__ acc) {
    __shared__ int   s_src[64];
    __shared__ int   s_dst[64];
    __shared__ float s_nrm[64];
    int t = threadIdx.x;
    int e0 = blockIdx.x * 64;
    if (t < 64) {
        s_src[t] = g_src[e0 + t];
        s_dst[t] = g_dst[e0 + t];
        s_nrm[t] = g_nrm[e0 + t];
    }
    __syncthreads();
    int j = t & 63;          // float4 lane within 256-wide row
    int es = t >> 6;         // 0..3
    #pragma unroll 4
    for (int eb = 0; eb < 64; eb += 4) {
        int e = eb + es;
        float n = s_nrm[e];
        float4 v = feat[(size_t)s_src[e] * 64 + j];
        v.x *= n; v.y *= n; v.z *= n; v.w *= n;
        float* p = acc + ((size_t)s_dst[e] * DD + j * 4);
        asm volatile("red.global.add.v4.f32 [%0], {%1,%2,%3,%4};"
                     :: "l"(p), "f"(v.x), "f"(v.y), "f"(v.z), "f"(v.w)
                     : "memory");
    }
}

// ---------------- SGEMM: C = A[M,K] @ B[K,N] + bias -----------------------
// 128x128 tile, BK=8, 256 threads, 8x8 per thread.
// FUSE=true: C = relu(..), C2 = C * dinv[row]^2 (init of next accumulator)
template <bool FUSE>
__global__ void __launch_bounds__(256) sgemm_kernel(
        const float* __restrict__ A, const float* __restrict__ B,
        const float* __restrict__ bias,
        float* __restrict__ C, float* __restrict__ C2,
        int M, int N, int K) {
    __shared__ float As[8][128];
    __shared__ float Bs[8][128];

    int tid  = threadIdx.x;
    int row0 = blockIdx.y * 128;
    int col0 = blockIdx.x * 128;

    int a_r = tid >> 1;            // 0..127
    int a_c = (tid & 1) * 4;       // 0 or 4
    int b_r = tid >> 5;            // 0..7
    int b_c = (tid & 31) * 4;

    int ty = tid >> 4, tx = tid & 15;

    const float* Aptr = A + (size_t)(row0 + a_r) * K + a_c;
    const float* Bptr = B + (size_t)b_r * N + col0 + b_c;
    bool a_ok = (row0 + a_r) < M;

    float acc[8][8];
    #pragma unroll
    for (int i = 0; i < 8; i++)
        #pragma unroll
        for (int jj = 0; jj < 8; jj++) acc[i][jj] = 0.0f;

    for (int k0 = 0; k0 < K; k0 += 8) {
        float4 av = a_ok ? *(const float4*)(Aptr + k0)
                         : make_float4(0.f, 0.f, 0.f, 0.f);
        As[a_c + 0][a_r] = av.x;
        As[a_c + 1][a_r] = av.y;
        As[a_c + 2][a_r] = av.z;
        As[a_c + 3][a_r] = av.w;
        *(float4*)&Bs[b_r][b_c] = *(const float4*)(Bptr + (size_t)k0 * N);
        __syncthreads();
        #pragma unroll
        for (int k = 0; k < 8; k++) {
            float ar[8], br[8];
            *(float4*)&ar[0] = *(const float4*)&As[k][ty * 8];
            *(float4*)&ar[4] = *(const float4*)&As[k][ty * 8 + 4];
            *(float4*)&br[0] = *(const float4*)&Bs[k][tx * 8];
            *(float4*)&br[4] = *(const float4*)&Bs[k][tx * 8 + 4];
            #pragma unroll
            for (int i = 0; i < 8; i++)
                #pragma unroll
                for (int jj = 0; jj < 8; jj++)
                    acc[i][jj] = fmaf(ar[i], br[jj], acc[i][jj]);
        }
        __syncthreads();
    }

    float bv[8];
    *(float4*)&bv[0] = *(const float4*)&bias[col0 + tx * 8];
    *(float4*)&bv[4] = *(const float4*)&bias[col0 + tx * 8 + 4];

    #pragma unroll
    for (int i = 0; i < 8; i++) {
        int r = row0 + ty * 8 + i;
        if (r >= M) break;
        float d2 = 0.0f;
        if (FUSE) { float d = g_dinv[r]; d2 = d * d; }
        float out[8];
        #pragma unroll
        for (int jj = 0; jj < 8; jj++) {
            float v = acc[i][jj] + bv[jj];
            if (FUSE) v = fmaxf(v, 0.0f);
            out[jj] = v;
        }
        float* cp = C + (size_t)r * N + col0 + tx * 8;
        *(float4*)cp       = *(float4*)&out[0];
        *(float4*)(cp + 4) = *(float4*)&out[4];
        if (FUSE) {
            float s2v[8];
            #pragma unroll
            for (int jj = 0; jj < 8; jj++) s2v[jj] = out[jj] * d2;
            float* c2p = C2 + (size_t)r * N + col0 + tx * 8;
            *(float4*)c2p       = *(float4*)&s2v[0];
            *(float4*)(c2p + 4) = *(float4*)&s2v[4];
        }
    }
}

// ---------------- launch ---------------------------------------------------
extern "C" void kernel_launch(void* const* d_in, const int* in_sizes, int n_in,
                              void* d_out, int out_size) {
    const float* x    = (const float*)d_in[0];
    const void*  ei   = d_in[1];
    const float* W1   = (const float*)d_in[2];
    const float* b1   = (const float*)d_in[3];
    const float* Wmu  = (const float*)d_in[4];
    const float* bmu  = (const float*)d_in[5];
    const float* Wlv  = (const float*)d_in[6];
    const float* blv  = (const float*)d_in[7];
    float* out_mu = (float*)d_out;
    float* out_lv = (float*)d_out + (size_t)NN * LAT;

    float* s1 = nullptr; float* z = nullptr; float* s2 = nullptr; float* dummy = nullptr;
    cudaGetSymbolAddress((void**)&s1, g_s1);
    cudaGetSymbolAddress((void**)&z,  g_z);
    cudaGetSymbolAddress((void**)&s2, g_s2);
    (void)dummy; (void)n_in; (void)in_sizes; (void)out_size;

    zero_deg_kernel<<<(NN + 255) / 256, 256>>>();
    detect_kernel<<<1, 1>>>(ei);
    count_deg_kernel<<<(NE + 255) / 256, 256>>>(ei);
    dinv_kernel<<<(NN + 255) / 256, 256>>>();
    edge_meta_kernel<<<(NE + 255) / 256, 256>>>(ei);

    // layer 1: s1 = agg(x) ; z = relu(s1 @ W1 + b1) ; s2 = z * dinv^2
    init_s1_kernel<<<(NN * 64 + 255) / 256, 256>>>((const float4*)x);
    scatter_kernel<<<NE / 64, 256>>>((const float4*)x, s1);
    sgemm_kernel<true><<<dim3(2, 391), 256>>>(s1, W1, b1, z, s2, NN, DD, DD);

    // layer 2/3 shared aggregation: s2 += scatter(z)
    scatter_kernel<<<NE / 64, 256>>>((const float4*)z, s2);
    sgemm_kernel<false><<<dim3(1, 391), 256>>>(s2, Wmu, bmu, out_mu, nullptr, NN, LAT, DD);
    sgemm_kernel<false><<<dim3(1, 391), 256>>>(s2, Wlv, blv, out_lv, nullptr, NN, LAT, DD);
}

// round 3
// speedup vs baseline: 1.3042x; 1.3042x over previous
#include <cuda_runtime.h>

#define NN 50000
#define NE 800000
#define DD 256
#define LAT 128
#define NBLK 196            // ceil(NN/256)

// ---------------- scratch (static __device__ globals; no allocs) ----------
static __device__ int   g_is64;
static __device__ int   g_deg[NN];
static __device__ float g_dinv[NN];
static __device__ int   g_rowstart[NN + 1];
static __device__ int   g_pos[NN];
static __device__ int   g_bsum[256];
static __device__ int   g_boff[256];
static __device__ int   g_csrc[NE];
static __device__ float g_cnrm[NE];
static __device__ __align__(16) float g_s1[(size_t)NN * DD];
static __device__ __align__(16) float g_z [(size_t)NN * DD];
static __device__ __align__(16) float g_s2[(size_t)NN * DD];

// ---------------- small prep kernels --------------------------------------
__global__ void zero_deg_kernel() {
    int i = blockIdx.x * blockDim.x + threadIdx.x;
    if (i < NN) g_deg[i] = 0;
}

// Detect whether edge_index is int64 or int32 (JAX w/o x64 downgrades to i32).
__global__ void detect_kernel(const void* ei) {
    const long long* p = (const long long*)ei;
    int ok = 1;
    for (int i = 0; i < 256; i++) {
        long long v = p[i];
        if (v < 0 || v >= NN) { ok = 0; break; }
    }
    g_is64 = ok;
}

__device__ __forceinline__ int load_idx(const void* ei, int pos) {
    if (g_is64) return (int)((const long long*)ei)[pos];
    return ((const int*)ei)[pos];
}

__global__ void count_deg_kernel(const void* __restrict__ ei) {
    int e = blockIdx.x * blockDim.x + threadIdx.x;
    if (e < NE) {
        int d = load_idx(ei, NE + e);
        atomicAdd(&g_deg[d], 1);
    }
}

__global__ void dinv_kernel() {
    int i = blockIdx.x * blockDim.x + threadIdx.x;
    if (i < NN) g_dinv[i] = rsqrtf((float)g_deg[i] + 1.0f);
}

// ---- 3-kernel exclusive scan of g_deg -> g_rowstart / g_pos ----
__global__ void scan1_kernel() {           // per-block sums
    __shared__ int s[256];
    int t = threadIdx.x;
    int i = blockIdx.x * 256 + t;
    s[t] = (i < NN) ? g_deg[i] : 0;
    __syncthreads();
    for (int o = 128; o > 0; o >>= 1) {
        if (t < o) s[t] += s[t + o];
        __syncthreads();
    }
    if (t == 0) g_bsum[blockIdx.x] = s[0];
}

__global__ void scan2_kernel() {           // scan of block sums (1 block)
    __shared__ int s[256];
    int t = threadIdx.x;
    int v = (t < NBLK) ? g_bsum[t] : 0;
    s[t] = v;
    __syncthreads();
    for (int o = 1; o < 256; o <<= 1) {
        int x = (t >= o) ? s[t - o] : 0;
        __syncthreads();
        s[t] += x;
        __syncthreads();
    }
    g_boff[t] = s[t] - v;                  // exclusive
}

__global__ void scan3_kernel() {           // final exclusive scan + pos init
    __shared__ int s[256];
    int t = threadIdx.x;
    int i = blockIdx.x * 256 + t;
    int v = (i < NN) ? g_deg[i] : 0;
    s[t] = v;
    __syncthreads();
    for (int o = 1; o < 256; o <<= 1) {
        int x = (t >= o) ? s[t - o] : 0;
        __syncthreads();
        s[t] += x;
        __syncthreads();
    }
    int excl = s[t] - v + g_boff[blockIdx.x];
    if (i < NN) {
        g_rowstart[i] = excl;
        g_pos[i] = excl;
        if (i == NN - 1) g_rowstart[NN] = excl + v;
    }
}

__global__ void csr_fill_kernel(const void* __restrict__ ei) {
    int e = blockIdx.x * blockDim.x + threadIdx.x;
    if (e < NE) {
        int s = load_idx(ei, e);
        int d = load_idx(ei, NE + e);
        int slot = atomicAdd(&g_pos[d], 1);
        g_csrc[slot] = s;
        g_cnrm[slot] = g_dinv[s] * g_dinv[d];
    }
}

// ---------------- CSR aggregation (gather, no atomics) ---------------------
// out[n,:] = dinv[n]^2 * feat[n,:] + sum_{e in CSR[n]} nrm_e * feat[src_e,:]
// 64 threads (one float4 lane each) per node; 4 nodes per 256-thread block.
__global__ void __launch_bounds__(256) agg_kernel(
        const float4* __restrict__ feat, float4* __restrict__ out) {
    int gid = (blockIdx.x * blockDim.x + threadIdx.x) >> 6;  // node
    int j   = threadIdx.x & 63;                              // float4 lane
    if (gid >= NN) return;

    int beg = g_rowstart[gid];
    int end = g_rowstart[gid + 1];
    float d  = g_dinv[gid];
    float d2 = d * d;

    float4 v = feat[(size_t)gid * 64 + j];
    float4 acc = make_float4(v.x * d2, v.y * d2, v.z * d2, v.w * d2);

    int e = beg;
    for (; e + 1 < end; e += 2) {
        int   s0 = g_csrc[e],     s1 = g_csrc[e + 1];
        float n0 = g_cnrm[e],     n1 = g_cnrm[e + 1];
        float4 u0 = feat[(size_t)s0 * 64 + j];
        float4 u1 = feat[(size_t)s1 * 64 + j];
        acc.x += n0 * u0.x + n1 * u1.x;
        acc.y += n0 * u0.y + n1 * u1.y;
        acc.z += n0 * u0.z + n1 * u1.z;
        acc.w += n0 * u0.w + n1 * u1.w;
    }
    if (e < end) {
        int   s0 = g_csrc[e];
        float n0 = g_cnrm[e];
        float4 u0 = feat[(size_t)s0 * 64 + j];
        acc.x += n0 * u0.x;
        acc.y += n0 * u0.y;
        acc.z += n0 * u0.z;
        acc.w += n0 * u0.w;
    }
    out[(size_t)gid * 64 + j] = acc;
}

// ---------------- SGEMM: C = A[M,K] @ B[K,N] + bias (opt. relu) ------------
// 128x128 tile, BK=8, 256 threads, 8x8 per thread.
template <bool RELU>
__global__ void __launch_bounds__(256) sgemm_kernel(
        const float* __restrict__ A, const float* __restrict__ B,
        const float* __restrict__ bias,
        float* __restrict__ C,
        int M, int N, int K) {
    __shared__ float As[8][128];
    __shared__ float Bs[8][128];

    int tid  = threadIdx.x;
    int row0 = blockIdx.y * 128;
    int col0 = blockIdx.x * 128;

    int a_r = tid >> 1;            // 0..127
    int a_c = (tid & 1) * 4;       // 0 or 4
    int b_r = tid >> 5;            // 0..7
    int b_c = (tid & 31) * 4;

    int ty = tid >> 4, tx = tid & 15;

    const float* Aptr = A + (size_t)(row0 + a_r) * K + a_c;
    const float* Bptr = B + (size_t)b_r * N + col0 + b_c;
    bool a_ok = (row0 + a_r) < M;

    float acc[8][8];
    #pragma unroll
    for (int i = 0; i < 8; i++)
        #pragma unroll
        for (int jj = 0; jj < 8; jj++) acc[i][jj] = 0.0f;

    for (int k0 = 0; k0 < K; k0 += 8) {
        float4 av = a_ok ? *(const float4*)(Aptr + k0)
                         : make_float4(0.f, 0.f, 0.f, 0.f);
        As[a_c + 0][a_r] = av.x;
        As[a_c + 1][a_r] = av.y;
        As[a_c + 2][a_r] = av.z;
        As[a_c + 3][a_r] = av.w;
        *(float4*)&Bs[b_r][b_c] = *(const float4*)(Bptr + (size_t)k0 * N);
        __syncthreads();
        #pragma unroll
        for (int k = 0; k < 8; k++) {
            float ar[8], br[8];
            *(float4*)&ar[0] = *(const float4*)&As[k][ty * 8];
            *(float4*)&ar[4] = *(const float4*)&As[k][ty * 8 + 4];
            *(float4*)&br[0] = *(const float4*)&Bs[k][tx * 8];
            *(float4*)&br[4] = *(const float4*)&Bs[k][tx * 8 + 4];
            #pragma unroll
            for (int i = 0; i < 8; i++)
                #pragma unroll
                for (int jj = 0; jj < 8; jj++)
                    acc[i][jj] = fmaf(ar[i], br[jj], acc[i][jj]);
        }
        __syncthreads();
    }

    float bv[8];
    *(float4*)&bv[0] = *(const float4*)&bias[col0 + tx * 8];
    *(float4*)&bv[4] = *(const float4*)&bias[col0 + tx * 8 + 4];

    #pragma unroll
    for (int i = 0; i < 8; i++) {
        int r = row0 + ty * 8 + i;
        if (r >= M) break;
        float out[8];
        #pragma unroll
        for (int jj = 0; jj < 8; jj++) {
            float v = acc[i][jj] + bv[jj];
            if (RELU) v = fmaxf(v, 0.0f);
            out[jj] = v;
        }
        float* cp = C + (size_t)r * N + col0 + tx * 8;
        *(float4*)cp       = *(float4*)&out[0];
        *(float4*)(cp + 4) = *(float4*)&out[4];
    }
}

// ---------------- launch ---------------------------------------------------
extern "C" void kernel_launch(void* const* d_in, const int* in_sizes, int n_in,
                              void* d_out, int out_size) {
    const float* x    = (const float*)d_in[0];
    const void*  ei   = d_in[1];
    const float* W1   = (const float*)d_in[2];
    const float* b1   = (const float*)d_in[3];
    const float* Wmu  = (const float*)d_in[4];
    const float* bmu  = (const float*)d_in[5];
    const float* Wlv  = (const float*)d_in[6];
    const float* blv  = (const float*)d_in[7];
    float* out_mu = (float*)d_out;
    float* out_lv = (float*)d_out + (size_t)NN * LAT;

    float* s1 = nullptr; float* z = nullptr; float* s2 = nullptr;
    cudaGetSymbolAddress((void**)&s1, g_s1);
    cudaGetSymbolAddress((void**)&z,  g_z);
    cudaGetSymbolAddress((void**)&s2, g_s2);
    (void)n_in; (void)in_sizes; (void)out_size;

    // ---- graph prep: degrees, norms, CSR ----
    zero_deg_kernel<<<NBLK, 256>>>();
    detect_kernel<<<1, 1>>>(ei);
    count_deg_kernel<<<(NE + 255) / 256, 256>>>(ei);
    dinv_kernel<<<NBLK, 256>>>();
    scan1_kernel<<<NBLK, 256>>>();
    scan2_kernel<<<1, 256>>>();
    scan3_kernel<<<NBLK, 256>>>();
    csr_fill_kernel<<<(NE + 255) / 256, 256>>>(ei);

    // ---- layer 1: s1 = agg(x) (incl. self term); z = relu(s1@W1 + b1) ----
    agg_kernel<<<(NN * 64 + 255) / 256, 256>>>((const float4*)x, (float4*)s1);
    sgemm_kernel<true><<<dim3(2, 391), 256>>>(s1, W1, b1, z, NN, DD, DD);

    // ---- layers 2/3 share the aggregation of z ----
    agg_kernel<<<(NN * 64 + 255) / 256, 256>>>((const float4*)z, (float4*)s2);
    sgemm_kernel<false><<<dim3(1, 391), 256>>>(s2, Wmu, bmu, out_mu, NN, LAT, DD);
    sgemm_kernel<false><<<dim3(1, 391), 256>>>(s2, Wlv, blv, out_lv, NN, LAT, DD);
}

// round 6
// speedup vs baseline: 2.3818x; 1.8263x over previous
#include <cuda_runtime.h>
#include <cuda_bf16.h>
#include <cstdint>

#define NN 50000
#define NPAD 50048          // 391 * 128
#define NE 800000
#define DD 256
#define LAT 128
#define NBLK 196            // ceil(NN/256)

// ---------------- scratch (static __device__ globals; no allocs) ----------
static __device__ int   g_is64;
static __device__ int   g_deg[NN];
static __device__ float g_dinv[NN];
static __device__ int   g_rowstart[NN + 1];
static __device__ int   g_pos[NN];
static __device__ int   g_bsum[256];
static __device__ int   g_boff[256];
static __device__ int   g_csrc[NE];
static __device__ float g_cnrm[NE];
static __device__ __align__(16) float         g_z [(size_t)NN * DD];
static __device__ __align__(16) __nv_bfloat16 g_a0[(size_t)NPAD * DD];   // A hi plane
static __device__ __align__(16) __nv_bfloat16 g_a1[(size_t)NPAD * DD];   // A lo plane
static __device__ __align__(16) __nv_bfloat16 g_wt1_0[DD * DD];          // W1^T hi [N,K]
static __device__ __align__(16) __nv_bfloat16 g_wt1_1[DD * DD];
static __device__ __align__(16) __nv_bfloat16 g_wtc_0[DD * DD];          // [Wmu|Wlv]^T hi
static __device__ __align__(16) __nv_bfloat16 g_wtc_1[DD * DD];
static __device__ float g_bcat[DD];

// ---------------- helpers ---------------------------------------------------
__device__ __forceinline__ uint32_t smem_u32(const void* p) {
    uint32_t a;
    asm("{ .reg .u64 t; cvta.to.shared.u64 t, %1; cvt.u32.u64 %0, t; }"
        : "=r"(a) : "l"(p));
    return a;
}

// ---------------- small prep kernels --------------------------------------
__global__ void zero_deg_kernel() {
    int i = blockIdx.x * blockDim.x + threadIdx.x;
    if (i < NN) g_deg[i] = 0;
}

__global__ void detect_kernel(const void* ei) {
    const long long* p = (const long long*)ei;
    int ok = 1;
    for (int i = 0; i < 256; i++) {
        long long v = p[i];
        if (v < 0 || v >= NN) { ok = 0; break; }
    }
    g_is64 = ok;
}

__device__ __forceinline__ int load_idx(const void* ei, int pos) {
    if (g_is64) return (int)((const long long*)ei)[pos];
    return ((const int*)ei)[pos];
}

__global__ void count_deg_kernel(const void* __restrict__ ei) {
    int e = blockIdx.x * blockDim.x + threadIdx.x;
    if (e < NE) atomicAdd(&g_deg[load_idx(ei, NE + e)], 1);
}

__global__ void dinv_kernel() {
    int i = blockIdx.x * blockDim.x + threadIdx.x;
    if (i < NN) g_dinv[i] = rsqrtf((float)g_deg[i] + 1.0f);
}

__global__ void scan1_kernel() {
    __shared__ int s[256];
    int t = threadIdx.x;
    int i = blockIdx.x * 256 + t;
    s[t] = (i < NN) ? g_deg[i] : 0;
    __syncthreads();
    for (int o = 128; o > 0; o >>= 1) {
        if (t < o) s[t] += s[t + o];
        __syncthreads();
    }
    if (t == 0) g_bsum[blockIdx.x] = s[0];
}

__global__ void scan2_kernel() {
    __shared__ int s[256];
    int t = threadIdx.x;
    int v = (t < NBLK) ? g_bsum[t] : 0;
    s[t] = v;
    __syncthreads();
    for (int o = 1; o < 256; o <<= 1) {
        int x = (t >= o) ? s[t - o] : 0;
        __syncthreads();
        s[t] += x;
        __syncthreads();
    }
    g_boff[t] = s[t] - v;
}

__global__ void scan3_kernel() {
    __shared__ int s[256];
    int t = threadIdx.x;
    int i = blockIdx.x * 256 + t;
    int v = (i < NN) ? g_deg[i] : 0;
    s[t] = v;
    __syncthreads();
    for (int o = 1; o < 256; o <<= 1) {
        int x = (t >= o) ? s[t - o] : 0;
        __syncthreads();
        s[t] += x;
        __syncthreads();
    }
    int excl = s[t] - v + g_boff[blockIdx.x];
    if (i < NN) {
        g_rowstart[i] = excl;
        g_pos[i] = excl;
        if (i == NN - 1) g_rowstart[NN] = excl + v;
    }
}

__global__ void csr_fill_kernel(const void* __restrict__ ei) {
    int e = blockIdx.x * blockDim.x + threadIdx.x;
    if (e < NE) {
        int s = load_idx(ei, e);
        int d = load_idx(ei, NE + e);
        int slot = atomicAdd(&g_pos[d], 1);
        g_csrc[slot] = s;
        g_cnrm[slot] = g_dinv[s] * g_dinv[d];
    }
}

// weight prep: transpose to [N,K], split to bf16 hi/lo; build concat weights+bias
__global__ void wprep_kernel(const float* __restrict__ W1,
                             const float* __restrict__ Wmu,
                             const float* __restrict__ Wlv,
                             const float* __restrict__ bmu,
                             const float* __restrict__ blv) {
    int idx = blockIdx.x * 256 + threadIdx.x;     // 65536
    int n = idx >> 8, k = idx & 255;
    float v1 = W1[k * DD + n];
    __nv_bfloat16 h = __float2bfloat16(v1);
    g_wt1_0[idx] = h;
    g_wt1_1[idx] = __float2bfloat16(v1 - __bfloat162float(h));
    float v2 = (n < LAT) ? Wmu[k * LAT + n] : Wlv[k * LAT + (n - LAT)];
    h = __float2bfloat16(v2);
    g_wtc_0[idx] = h;
    g_wtc_1[idx] = __float2bfloat16(v2 - __bfloat162float(h));
    if (idx < DD) g_bcat[idx] = (idx < LAT) ? bmu[idx] : blv[idx - LAT];
}

// ---------------- CSR aggregation -> split bf16 planes ---------------------
__device__ __forceinline__ void split_store(__nv_bfloat16* p0, __nv_bfloat16* p1,
                                            size_t off, float4 v) {
    __nv_bfloat16 h[4], l[4];
    float vv[4] = {v.x, v.y, v.z, v.w};
    #pragma unroll
    for (int i = 0; i < 4; i++) {
        h[i] = __float2bfloat16(vv[i]);
        l[i] = __float2bfloat16(vv[i] - __bfloat162float(h[i]));
    }
    *(uint2*)(p0 + off) = *(uint2*)h;
    *(uint2*)(p1 + off) = *(uint2*)l;
}

__global__ void __launch_bounds__(256) agg_kernel(
        const float4* __restrict__ feat,
        __nv_bfloat16* __restrict__ p0, __nv_bfloat16* __restrict__ p1) {
    int gid = (blockIdx.x * blockDim.x + threadIdx.x) >> 6;
    int j   = threadIdx.x & 63;
    if (gid >= NN) return;

    int beg = g_rowstart[gid];
    int end = g_rowstart[gid + 1];
    float d  = g_dinv[gid];
    float d2 = d * d;

    float4 v = feat[(size_t)gid * 64 + j];
    float4 acc = make_float4(v.x * d2, v.y * d2, v.z * d2, v.w * d2);

    int e = beg;
    for (; e + 1 < end; e += 2) {
        int   s0 = g_csrc[e],     s1 = g_csrc[e + 1];
        float n0 = g_cnrm[e],     n1 = g_cnrm[e + 1];
        float4 u0 = feat[(size_t)s0 * 64 + j];
        float4 u1 = feat[(size_t)s1 * 64 + j];
        acc.x += n0 * u0.x + n1 * u1.x;
        acc.y += n0 * u0.y + n1 * u1.y;
        acc.z += n0 * u0.z + n1 * u1.z;
        acc.w += n0 * u0.w + n1 * u1.w;
    }
    if (e < end) {
        int   s0 = g_csrc[e];
        float n0 = g_cnrm[e];
        float4 u0 = feat[(size_t)s0 * 64 + j];
        acc.x += n0 * u0.x;
        acc.y += n0 * u0.y;
        acc.z += n0 * u0.z;
        acc.w += n0 * u0.w;
    }
    split_store(p0, p1, (size_t)gid * DD + 4 * j, acc);
}

// ---------------- mma.sync bf16 GEMM ---------------------------------------
// C[M,256] = (A0+A1) @ (B0+B1)^T  (B stored [N,K], K-contiguous)
// 3-product split: a0b0 + a0b1 + a1b0, fp32 accumulators.
// BM=128, BN=128, BK=32, 8 warps (warp tile 32x64), cp.async double buffer.
// smem rows padded to 40 bf16 (80 B) -> ldmatrix conflict-free.
#define SMEM_ARR   10240                 // 128 rows * 80 B
#define SMEM_STAGE (4 * SMEM_ARR)        // A0,A1,B0,B1
#define SMEM_TOT_G (2 * SMEM_STAGE)      // 81920 B

__device__ __forceinline__ void ldmx4(uint32_t* r, uint32_t addr) {
    asm volatile("ldmatrix.sync.aligned.m8n8.x4.shared.b16 {%0,%1,%2,%3}, [%4];"
                 : "=r"(r[0]), "=r"(r[1]), "=r"(r[2]), "=r"(r[3]) : "r"(addr));
}
__device__ __forceinline__ void ldmx2(uint32_t* r, uint32_t addr) {
    asm volatile("ldmatrix.sync.aligned.m8n8.x2.shared.b16 {%0,%1}, [%2];"
                 : "=r"(r[0]), "=r"(r[1]) : "r"(addr));
}
__device__ __forceinline__ void mma16816(float* c, const uint32_t* a,
                                         const uint32_t* b) {
    asm volatile(
        "mma.sync.aligned.m16n8k16.row.col.f32.bf16.bf16.f32 "
        "{%0,%1,%2,%3}, {%4,%5,%6,%7}, {%8,%9}, {%0,%1,%2,%3};"
        : "+f"(c[0]), "+f"(c[1]), "+f"(c[2]), "+f"(c[3])
        : "r"(a[0]), "r"(a[1]), "r"(a[2]), "r"(a[3]), "r"(b[0]), "r"(b[1]));
}

template <int EPI>
__global__ void __launch_bounds__(256) gemm_mma_kernel(
        const __nv_bfloat16* __restrict__ A0, const __nv_bfloat16* __restrict__ A1,
        const __nv_bfloat16* __restrict__ B0, const __nv_bfloat16* __restrict__ B1,
        const float* __restrict__ bias,
        float* __restrict__ out0, float* __restrict__ out1) {
    extern __shared__ char smem[];
    uint32_t sb = smem_u32(smem);
    int tid = threadIdx.x;
    int lane = tid & 31, w = tid >> 5;
    int warp_m = w & 3, warp_n = w >> 2;
    int row0 = blockIdx.x * 128;
    int col0 = blockIdx.y * 128;

    auto load_chunk = [&](int st, int c) {
        #pragma unroll
        for (int it = 0; it < 8; it++) {
            int i   = tid + it * 256;
            int u   = i & 3;                 // 16B unit within 64B row-chunk
            int row = (i >> 2) & 127;
            int arr = i >> 9;                // 0:A0 1:A1 2:B0 3:B1
            const __nv_bfloat16* base = (arr == 0) ? A0 : (arr == 1) ? A1
                                      : (arr == 2) ? B0 : B1;
            int grow = (arr < 2) ? (row0 + row) : (col0 + row);
            const void* src = base + (size_t)grow * DD + c * 32 + u * 8;
            uint32_t dst = sb + st * SMEM_STAGE + arr * SMEM_ARR + row * 80 + u * 16;
            asm volatile("cp.async.cg.shared.global [%0], [%1], 16;"
                         :: "r"(dst), "l"(src));
        }
        asm volatile("cp.async.commit_group;" ::: "memory");
    };

    float acc[2][8][4];
    #pragma unroll
    for (int i = 0; i < 2; i++)
        #pragma unroll
        for (int j = 0; j < 8; j++)
            #pragma unroll
            for (int q = 0; q < 4; q++) acc[i][j][q] = 0.0f;

    load_chunk(0, 0);
    asm volatile("cp.async.wait_group 0;" ::: "memory");
    __syncthreads();

    int ar = 32 * warp_m + (lane & 15);
    int ac = (lane >> 4) << 3;
    int br = 64 * warp_n + (lane & 7);
    int bc = ((lane >> 3) & 1) << 3;

    for (int c = 0; c < 8; c++) {
        int st = c & 1;
        if (c < 7) load_chunk(st ^ 1, c + 1);

        uint32_t sA0 = sb + st * SMEM_STAGE;
        uint32_t sA1 = sA0 + SMEM_ARR;
        uint32_t sB0 = sA0 + 2 * SMEM_ARR;
        uint32_t sB1 = sA0 + 3 * SMEM_ARR;

        #pragma unroll
        for (int s = 0; s < 2; s++) {
            uint32_t a0f[2][4], a1f[2][4];
            #pragma unroll
            for (int i = 0; i < 2; i++) {
                uint32_t off = (uint32_t)(ar + 16 * i) * 80 + (ac + 16 * s) * 2;
                ldmx4(a0f[i], sA0 + off);
                ldmx4(a1f[i], sA1 + off);
            }
            #pragma unroll
            for (int j = 0; j < 8; j++) {
                uint32_t b0f[2], b1f[2];
                uint32_t off = (uint32_t)(br + 8 * j) * 80 + (bc + 16 * s) * 2;
                ldmx2(b0f, sB0 + off);
                ldmx2(b1f, sB1 + off);
                #pragma unroll
                for (int i = 0; i < 2; i++) {
                    mma16816(acc[i][j], a0f[i], b0f);
                    mma16816(acc[i][j], a0f[i], b1f);
                    mma16816(acc[i][j], a1f[i], b0f);
                }
            }
        }
        asm volatile("cp.async.wait_group 0;" ::: "memory");
        __syncthreads();
    }

    // ---- epilogue ----
    #pragma unroll
    for (int i = 0; i < 2; i++) {
        int r = row0 + 32 * warp_m + 16 * i + (lane >> 2);
        #pragma unroll
        for (int j = 0; j < 8; j++) {
            int cg = col0 + 64 * warp_n + 8 * j + ((lane & 3) << 1);
            float b0v = bias[cg], b1v = bias[cg + 1];
            float v0 = acc[i][j][0] + b0v, v1 = acc[i][j][1] + b1v;
            float v2 = acc[i][j][2] + b0v, v3 = acc[i][j][3] + b1v;
            if (EPI == 1) {
                v0 = fmaxf(v0, 0.0f); v1 = fmaxf(v1, 0.0f);
                v2 = fmaxf(v2, 0.0f); v3 = fmaxf(v3, 0.0f);
                if (r < NN)
                    *(float2*)(out0 + (size_t)r * DD + cg) = make_float2(v0, v1);
                if (r + 8 < NN)
                    *(float2*)(out0 + (size_t)(r + 8) * DD + cg) = make_float2(v2, v3);
            } else {
                float* o  = (cg < LAT) ? out0 + (size_t)r * LAT + cg
                                       : out1 + (size_t)r * LAT + (cg - LAT);
                float* o8 = (cg < LAT) ? out0 + (size_t)(r + 8) * LAT + cg
                                       : out1 + (size_t)(r + 8) * LAT + (cg - LAT);
                if (r < NN)     *(float2*)o  = make_float2(v0, v1);
                if (r + 8 < NN) *(float2*)o8 = make_float2(v2, v3);
            }
        }
    }
}

// ---------------- launch ---------------------------------------------------
extern "C" void kernel_launch(void* const* d_in, const int* in_sizes, int n_in,
                              void* d_out, int out_size) {
    const float* x    = (const float*)d_in[0];
    const void*  ei   = d_in[1];
    const float* W1   = (const float*)d_in[2];
    const float* b1   = (const float*)d_in[3];
    const float* Wmu  = (const float*)d_in[4];
    const float* bmu  = (const float*)d_in[5];
    const float* Wlv  = (const float*)d_in[6];
    const float* blv  = (const float*)d_in[7];
    float* out_mu = (float*)d_out;
    float* out_lv = (float*)d_out + (size_t)NN * LAT;

    float* z = nullptr;
    __nv_bfloat16 *a0 = nullptr, *a1 = nullptr;
    __nv_bfloat16 *wt10 = nullptr, *wt11 = nullptr, *wtc0 = nullptr, *wtc1 = nullptr;
    float* bcat = nullptr;
    cudaGetSymbolAddress((void**)&z,    g_z);
    cudaGetSymbolAddress((void**)&a0,   g_a0);
    cudaGetSymbolAddress((void**)&a1,   g_a1);
    cudaGetSymbolAddress((void**)&wt10, g_wt1_0);
    cudaGetSymbolAddress((void**)&wt11, g_wt1_1);
    cudaGetSymbolAddress((void**)&wtc0, g_wtc_0);
    cudaGetSymbolAddress((void**)&wtc1, g_wtc_1);
    cudaGetSymbolAddress((void**)&bcat, g_bcat);
    (void)n_in; (void)in_sizes; (void)out_size;

    cudaFuncSetAttribute(gemm_mma_kernel<1>,
                         cudaFuncAttributeMaxDynamicSharedMemorySize, SMEM_TOT_G);
    cudaFuncSetAttribute(gemm_mma_kernel<2>,
                         cudaFuncAttributeMaxDynamicSharedMemorySize, SMEM_TOT_G);

    // ---- graph prep ----
    zero_deg_kernel<<<NBLK, 256>>>();
    detect_kernel<<<1, 1>>>(ei);
    count_deg_kernel<<<(NE + 255) / 256, 256>>>(ei);
    dinv_kernel<<<NBLK, 256>>>();
    scan1_kernel<<<NBLK, 256>>>();
    scan2_kernel<<<1, 256>>>();
    scan3_kernel<<<NBLK, 256>>>();
    csr_fill_kernel<<<(NE + 255) / 256, 256>>>(ei);
    wprep_kernel<<<256, 256>>>(W1, Wmu, Wlv, bmu, blv);

    // ---- layer 1 ----
    agg_kernel<<<(NN * 64 + 255) / 256, 256>>>((const float4*)x, a0, a1);
    gemm_mma_kernel<1><<<dim3(NPAD / 128, 2), 256, SMEM_TOT_G>>>(a0, a1, wt10, wt11,
                                                                 b1, z, nullptr);

    // ---- layers 2/3 (shared aggregation, fused N=256 GEMM) ----
    agg_kernel<<<(NN * 64 + 255) / 256, 256>>>((const float4*)z, a0, a1);
    gemm_mma_kernel<2><<<dim3(NPAD / 128, 2), 256, SMEM_TOT_G>>>(a0, a1, wtc0, wtc1,
                                                                 bcat, out_mu, out_lv);
}